// round 10
// baseline (speedup 1.0000x reference)
#include <cuda_runtime.h>
#include <math.h>
#include <stddef.h>

#define BSZ 256
#define SSZ 128
#define ESZ 256
#define HSZ 512
#define GSZ 2048   // 4*H
#define NC  2560   // 2048 gates + 512 (proj or q)
#define NB2 4096   // 2*GSZ combined xg cols

// ---------- device scratch ----------
__device__ float  g_WencT[HSZ * NC];
__device__ float  g_WdecT[HSZ * NC];
__device__ float  g_WihT[ESZ * NB2];
__device__ float  g_emb[(size_t)BSZ * SSZ * ESZ];
__device__ float  g_xg_enc[(size_t)BSZ * SSZ * GSZ];
__device__ float  g_xg_dec[(size_t)BSZ * SSZ * GSZ];
__device__ float  g_proj[(size_t)BSZ * SSZ * HSZ];
__device__ float  g_C[BSZ * GSZ];
__device__ float  g_h[2][BSZ * HSZ];
__device__ float  g_c[BSZ * HSZ];
__device__ float  g_q[BSZ * HSZ];
__device__ float  g_xg0[GSZ];
__device__ int    g_mask[BSZ * SSZ];
__device__ int    g_sel[BSZ];

// ---------- tanh: libdevice ----------
__device__ __forceinline__ float xtanh(float x) { return tanhf(x); }
// logistic(x) = 1 / (1 + exp(-x)) with accurate libdevice expf and true division
// (modern XLA:GPU lowers HLO logistic directly, not via the tanh expander)
__device__ __forceinline__ float sigf(float x) {
    return __fdiv_rn(1.0f, __fadd_rn(1.0f, expf(-x)));
}

// ---------- weight transposes ----------
__global__ void transpose_kernel(const float* __restrict__ encWhh, const float* __restrict__ W1,
                                 const float* __restrict__ decWhh, const float* __restrict__ W2) {
    int i = blockIdx.x * blockDim.x + threadIdx.x;
    if (i >= HSZ * NC) return;
    int k = i / NC, n = i % NC;
    g_WencT[i] = (n < GSZ) ? encWhh[n * HSZ + k] : W1[(n - GSZ) * HSZ + k];
    g_WdecT[i] = (n < GSZ) ? decWhh[n * HSZ + k] : W2[(n - GSZ) * HSZ + k];
}
__global__ void wiht_kernel(const float* __restrict__ encWih, const float* __restrict__ decWih) {
    int i = blockIdx.x * blockDim.x + threadIdx.x;
    if (i >= ESZ * NB2) return;
    int k = i / NB2, n = i % NB2;
    g_WihT[i] = (n < GSZ) ? encWih[n * ESZ + k] : decWih[(n - GSZ) * ESZ + k];
}

// ---------- emb: K=2 fma chain + fp32 bias ----------
__global__ void emb_kernel(const float* __restrict__ inputs, const float* __restrict__ embW,
                           const float* __restrict__ embB) {
    int i = blockIdx.x * blockDim.x + threadIdx.x;
    if (i >= BSZ * SSZ * ESZ) return;
    int e = i % ESZ, bs = i / ESZ;
    float in0 = inputs[(size_t)bs * 2], in1 = inputs[(size_t)bs * 2 + 1];
    float mm = fmaf(in1, embW[2 * e + 1], __fmul_rn(in0, embW[2 * e]));
    g_emb[i] = __fadd_rn(mm, embB[e]);
}

// ---------- decoder step-0 input gates ----------
__global__ void xg0_kernel(const float* __restrict__ decWih, const float* __restrict__ dbih,
                           const float* __restrict__ dbhh, const float* __restrict__ dec0) {
    int n = blockIdx.x * blockDim.x + threadIdx.x;
    if (n >= GSZ) return;
    float acc = 0.f;
    for (int e = 0; e < ESZ; e++) acc = fmaf(dec0[e], decWih[n * ESZ + e], acc);
    g_xg0[n] = __fadd_rn(__fadd_rn(acc, dbih[n]), dbhh[n]);
}

// ---------- state init ----------
__global__ void init_kernel(const float* __restrict__ h0, const float* __restrict__ c0,
                            const float* __restrict__ inputs) {
    int i = blockIdx.x * blockDim.x + threadIdx.x;
    if (i < BSZ * HSZ) {
        g_h[0][i] = h0[i & (HSZ - 1)];
        g_c[i]    = c0[i & (HSZ - 1)];
    }
    if (i < BSZ * SSZ) g_mask[i] = (inputs[(size_t)i * 2] > 0.0f) ? 1 : 0;
}

// ---------- xg precompute GEMM: [32768,4096] = emb @ WihT, fp32 ascending ----------
__global__ void __launch_bounds__(256) xg_gemm(const float* __restrict__ ebih, const float* __restrict__ ebhh,
                                               const float* __restrict__ dbih, const float* __restrict__ dbhh) {
    __shared__ __align__(16) float As[16][64 + 4];
    __shared__ __align__(16) float Bs[16][64];
    const int tid = threadIdx.x;
    const int row0 = blockIdx.y * 64;
    const int n0 = blockIdx.x * 64;
    const int lr = tid >> 2, lk = (tid & 3) << 2;
    const int bk = tid >> 4, bn = (tid & 15) << 2;
    const int tm = tid & 15, tn = tid >> 4;

    float acc[4][4];
#pragma unroll
    for (int i = 0; i < 4; i++)
#pragma unroll
        for (int j = 0; j < 4; j++) acc[i][j] = 0.f;

    {
        float4 av = *reinterpret_cast<const float4*>(g_emb + (size_t)(row0 + lr) * ESZ + lk);
        As[lk + 0][lr] = av.x; As[lk + 1][lr] = av.y;
        As[lk + 2][lr] = av.z; As[lk + 3][lr] = av.w;
        *reinterpret_cast<float4*>(&Bs[bk][bn]) =
            *reinterpret_cast<const float4*>(g_WihT + (size_t)bk * NB2 + n0 + bn);
    }
    __syncthreads();

    const int NKC = ESZ / 16;  // 16
    for (int kc = 0; kc < NKC; kc++) {
        float4 av; float4 bv;
        if (kc + 1 < NKC) {
            int k0 = (kc + 1) * 16;
            av = *reinterpret_cast<const float4*>(g_emb + (size_t)(row0 + lr) * ESZ + k0 + lk);
            bv = *reinterpret_cast<const float4*>(g_WihT + (size_t)(k0 + bk) * NB2 + n0 + bn);
        }
#pragma unroll
        for (int k = 0; k < 16; k++) {
            float4 a4 = *reinterpret_cast<const float4*>(&As[k][tm * 4]);
            float4 b4 = *reinterpret_cast<const float4*>(&Bs[k][tn * 4]);
            float ar[4] = {a4.x, a4.y, a4.z, a4.w};
            float br[4] = {b4.x, b4.y, b4.z, b4.w};
#pragma unroll
            for (int i = 0; i < 4; i++)
#pragma unroll
                for (int j = 0; j < 4; j++) acc[i][j] = fmaf(ar[i], br[j], acc[i][j]);
        }
        __syncthreads();
        if (kc + 1 < NKC) {
            As[lk + 0][lr] = av.x; As[lk + 1][lr] = av.y;
            As[lk + 2][lr] = av.z; As[lk + 3][lr] = av.w;
            *reinterpret_cast<float4*>(&Bs[bk][bn]) = bv;
            __syncthreads();
        }
    }

#pragma unroll
    for (int i = 0; i < 4; i++) {
        size_t row = row0 + tm * 4 + i;
#pragma unroll
        for (int j = 0; j < 4; j++) {
            int n = n0 + tn * 4 + j;
            if (n < GSZ)
                g_xg_enc[row * GSZ + n] = __fadd_rn(__fadd_rn(acc[i][j], ebih[n]), ebhh[n]);
            else {
                int nd = n - GSZ;
                g_xg_dec[row * GSZ + nd] = __fadd_rn(__fadd_rn(acc[i][j], dbih[nd]), dbhh[nd]);
            }
        }
    }
}

// ---------- fused step GEMM: [256,2560] = A[256,512] @ WT[512,2560], fp32 ascending ----------
#define BM 64
#define BN 80
#define BK 16
__global__ void __launch_bounds__(256) gemm_step(const float* __restrict__ A,
                                                 const float* __restrict__ WT,
                                                 float* __restrict__ dst2,
                                                 const float* __restrict__ bias2,
                                                 int stride2) {
    __shared__ __align__(16) float As[BK][BM + 4];
    __shared__ __align__(16) float Bs[BK][BN];

    const int tid = threadIdx.x;
    const int tm = tid & 15;
    const int tn = tid >> 4;
    const int row0 = blockIdx.y * BM;
    const int n0 = blockIdx.x * BN;
    const int lr = tid >> 2, lk = (tid & 3) << 2;
    const int bk = tid >> 4, bn = tid & 15;

    float acc[4][5];
#pragma unroll
    for (int i = 0; i < 4; i++)
#pragma unroll
        for (int j = 0; j < 5; j++) acc[i][j] = 0.f;

    {
        float4 av = *reinterpret_cast<const float4*>(A + (size_t)(row0 + lr) * HSZ + lk);
        As[lk + 0][lr] = av.x; As[lk + 1][lr] = av.y;
        As[lk + 2][lr] = av.z; As[lk + 3][lr] = av.w;
#pragma unroll
        for (int j = 0; j < 5; j++)
            Bs[bk][bn + 16 * j] = WT[(size_t)bk * NC + n0 + bn + 16 * j];
    }
    __syncthreads();

    const int NKC = HSZ / BK;  // 32
    for (int kc = 0; kc < NKC; kc++) {
        float4 av;
        float bv[5];
        if (kc + 1 < NKC) {
            int k0 = (kc + 1) * BK;
            av = *reinterpret_cast<const float4*>(A + (size_t)(row0 + lr) * HSZ + k0 + lk);
#pragma unroll
            for (int j = 0; j < 5; j++)
                bv[j] = WT[(size_t)(k0 + bk) * NC + n0 + bn + 16 * j];
        }
#pragma unroll
        for (int k = 0; k < BK; k++) {
            float4 a4 = *reinterpret_cast<const float4*>(&As[k][tm * 4]);
            float ar[4] = {a4.x, a4.y, a4.z, a4.w};
            float br[5];
#pragma unroll
            for (int j = 0; j < 5; j++) br[j] = Bs[k][tn + 16 * j];
#pragma unroll
            for (int i = 0; i < 4; i++)
#pragma unroll
                for (int j = 0; j < 5; j++) acc[i][j] = fmaf(ar[i], br[j], acc[i][j]);
        }
        __syncthreads();
        if (kc + 1 < NKC) {
            As[lk + 0][lr] = av.x; As[lk + 1][lr] = av.y;
            As[lk + 2][lr] = av.z; As[lk + 3][lr] = av.w;
#pragma unroll
            for (int j = 0; j < 5; j++) Bs[bk][bn + 16 * j] = bv[j];
            __syncthreads();
        }
    }

#pragma unroll
    for (int i = 0; i < 4; i++) {
        int b = row0 + tm * 4 + i;
#pragma unroll
        for (int j = 0; j < 5; j++) {
            int n = n0 + tn + 16 * j;
            if (n < GSZ) {
                g_C[(size_t)b * GSZ + n] = acc[i][j];
            } else if (dst2) {
                int n2 = n - GSZ;
                dst2[(size_t)b * stride2 + n2] = __fadd_rn(acc[i][j], bias2[n2]);
            }
        }
    }
}

// ---------- LSTM cell: unfused mul/add, libdevice tanh, exp-based logistic ----------
__global__ void __launch_bounds__(256) cell_kernel(float* __restrict__ h_out,
                                                   const float* __restrict__ xg,
                                                   size_t bstride,
                                                   const int* __restrict__ sel) {
    int idx = blockIdx.x * blockDim.x + threadIdx.x;
    int b = idx >> 9, hh = idx & (HSZ - 1);
    const float* Cb = g_C + (size_t)b * GSZ;
    const float* xr = xg + (size_t)b * bstride + (sel ? (size_t)sel[b] * GSZ : 0);
    float gi = __fadd_rn(xr[hh],           Cb[hh]);
    float gf = __fadd_rn(xr[HSZ + hh],     Cb[HSZ + hh]);
    float gg = __fadd_rn(xr[2 * HSZ + hh], Cb[2 * HSZ + hh]);
    float go = __fadd_rn(xr[3 * HSZ + hh], Cb[3 * HSZ + hh]);
    float si = sigf(gi), sf = sigf(gf), so = sigf(go);
    float tg = xtanh(gg);
    float cn = __fadd_rn(__fmul_rn(sf, g_c[idx]), __fmul_rn(si, tg));
    g_c[idx] = cn;
    h_out[idx] = __fmul_rn(so, xtanh(cn));
}

// ---------- attention + softmax + argmax(probs, first occurrence) ----------
__global__ void __launch_bounds__(256) attn_kernel(int step,
                                                   const float* __restrict__ V,
                                                   float* __restrict__ out_probs,
                                                   float* __restrict__ out_idx) {
    int b = blockIdx.x;
    int tid = threadIdx.x, lane = tid & 31, w = tid >> 5;
    __shared__ float qs[HSZ];
    __shared__ float Vs[HSZ];
    __shared__ float us[SSZ];
    __shared__ float es[SSZ];
    __shared__ float ps[SSZ];
    __shared__ float s_mx, s_sum;
    __shared__ int s_idx;

    for (int i = tid; i < HSZ; i += 256) {
        qs[i] = g_q[(size_t)b * HSZ + i];
        Vs[i] = V[i];
    }
    __syncthreads();

    // u[s] = sum_h tanh(proj+q)*V : fp32, lane-strided (k = lane + 32m) ascending, xor tree
    for (int s = w; s < SSZ; s += 8) {
        const float* pr = g_proj + ((size_t)b * SSZ + s) * HSZ;
        float acc = 0.f;
        for (int h = lane; h < HSZ; h += 32)
            acc = fmaf(xtanh(__fadd_rn(pr[h], qs[h])), Vs[h], acc);
#pragma unroll
        for (int o = 16; o; o >>= 1)
            acc = __fadd_rn(acc, __shfl_xor_sync(0xffffffffu, acc, o));
        if (lane == 0) us[s] = g_mask[b * SSZ + s] ? acc : -10000.0f;
    }
    __syncthreads();

    if (w == 0) {
        float mv = fmaxf(us[lane], fmaxf(us[lane + 32], fmaxf(us[lane + 64], us[lane + 96])));
#pragma unroll
        for (int o = 16; o; o >>= 1) mv = fmaxf(mv, __shfl_xor_sync(0xffffffffu, mv, o));
        if (lane == 0) s_mx = mv;
    }
    __syncthreads();

    if (tid < SSZ) es[tid] = expf(__fadd_rn(us[tid], -s_mx));
    __syncthreads();

    if (w == 0) {
        float sv = __fadd_rn(__fadd_rn(es[lane], es[lane + 32]),
                             __fadd_rn(es[lane + 64], es[lane + 96]));
#pragma unroll
        for (int o = 16; o; o >>= 1)
            sv = __fadd_rn(sv, __shfl_xor_sync(0xffffffffu, sv, o));
        if (lane == 0) s_sum = sv;
    }
    __syncthreads();

    if (tid < SSZ) {
        float p = __fdiv_rn(es[tid], s_sum);
        ps[tid] = p;
        out_probs[((size_t)step * BSZ + b) * SSZ + tid] = p;
    }
    __syncthreads();

    if (w == 0) {
        float bv = -1.0f;
        int bi = 0;
#pragma unroll
        for (int k = 0; k < 4; k++) {
            int s = lane + 32 * k;
            float v = ps[s];
            if (v > bv) { bv = v; bi = s; }
        }
#pragma unroll
        for (int o = 16; o; o >>= 1) {
            float ov = __shfl_xor_sync(0xffffffffu, bv, o);
            int oi = __shfl_xor_sync(0xffffffffu, bi, o);
            if (ov > bv || (ov == bv && oi < bi)) { bv = ov; bi = oi; }
        }
        if (lane == 0) s_idx = bi;
    }
    __syncthreads();

    if (tid == 0) {
        int bi = s_idx;
        g_mask[b * SSZ + bi] = 0;
        g_sel[b] = bi;
        if (out_idx) out_idx[(size_t)b * SSZ + step] = (float)bi;
    }
}

// ---------- host ----------
extern "C" void kernel_launch(void* const* d_in, const int* in_sizes, int n_in,
                              void* d_out, int out_size) {
    const float* inputs  = (const float*)d_in[0];
    const float* emb_W   = (const float*)d_in[2];
    const float* emb_b   = (const float*)d_in[3];
    const float* enc_Wih = (const float*)d_in[4];
    const float* enc_Whh = (const float*)d_in[5];
    const float* enc_bih = (const float*)d_in[6];
    const float* enc_bhh = (const float*)d_in[7];
    const float* h0      = (const float*)d_in[8];
    const float* c0      = (const float*)d_in[9];
    const float* dec0    = (const float*)d_in[10];
    const float* dec_Wih = (const float*)d_in[11];
    const float* dec_Whh = (const float*)d_in[12];
    const float* dec_bih = (const float*)d_in[13];
    const float* dec_bhh = (const float*)d_in[14];
    const float* W1      = (const float*)d_in[15];
    const float* b1      = (const float*)d_in[16];
    const float* W2      = (const float*)d_in[17];
    const float* b2      = (const float*)d_in[18];
    const float* V       = (const float*)d_in[19];

    float *pWencT, *pWdecT, *pproj, *pq, *ph, *pxg_enc, *pxg_dec, *pxg0;
    int* psel;
    cudaGetSymbolAddress((void**)&pWencT,  g_WencT);
    cudaGetSymbolAddress((void**)&pWdecT,  g_WdecT);
    cudaGetSymbolAddress((void**)&pproj,   g_proj);
    cudaGetSymbolAddress((void**)&pq,      g_q);
    cudaGetSymbolAddress((void**)&ph,      g_h);
    cudaGetSymbolAddress((void**)&pxg_enc, g_xg_enc);
    cudaGetSymbolAddress((void**)&pxg_dec, g_xg_dec);
    cudaGetSymbolAddress((void**)&pxg0,    g_xg0);
    cudaGetSymbolAddress((void**)&psel,    g_sel);
    float* hbuf[2] = {ph, ph + BSZ * HSZ};

    transpose_kernel<<<(HSZ * NC + 255) / 256, 256>>>(enc_Whh, W1, dec_Whh, W2);
    wiht_kernel<<<(ESZ * NB2 + 255) / 256, 256>>>(enc_Wih, dec_Wih);
    emb_kernel<<<(BSZ * SSZ * ESZ + 255) / 256, 256>>>(inputs, emb_W, emb_b);
    xg0_kernel<<<GSZ / 256, 256>>>(dec_Wih, dec_bih, dec_bhh, dec0);
    init_kernel<<<(BSZ * HSZ + 255) / 256, 256>>>(h0, c0, inputs);
    {
        dim3 gx(NB2 / 64, BSZ * SSZ / 64);  // 64 x 512
        xg_gemm<<<gx, 256>>>(enc_bih, enc_bhh, dec_bih, dec_bhh);
    }

    float* out_probs = (float*)d_out;
    const size_t PROBS_N = (size_t)SSZ * BSZ * SSZ;
    float* out_idx = ((size_t)out_size >= PROBS_N + (size_t)BSZ * SSZ)
                         ? out_probs + PROBS_N : nullptr;

    dim3 gg(NC / BN, BSZ / BM);   // 32 x 4 = 128 blocks
    const size_t XB = (size_t)SSZ * GSZ;
    int cur = 0;

    // encoder
    for (int t = 0; t < SSZ; t++) {
        gemm_step<<<gg, 256>>>(hbuf[cur], pWencT,
                               (t > 0) ? (pproj + (size_t)(t - 1) * HSZ) : nullptr,
                               b1, SSZ * HSZ);
        cell_kernel<<<BSZ * HSZ / 256, 256>>>(hbuf[cur ^ 1],
                                              pxg_enc + (size_t)t * GSZ, XB, nullptr);
        cur ^= 1;
    }
    gemm_step<<<gg, 256>>>(hbuf[cur], pWencT, pproj + (size_t)(SSZ - 1) * HSZ, b1, SSZ * HSZ);

    // decoder
    for (int t = 0; t < SSZ; t++) {
        gemm_step<<<gg, 256>>>(hbuf[cur], pWdecT, (t > 0) ? pq : nullptr, b2, HSZ);
        if (t > 0)
            attn_kernel<<<BSZ, 256>>>(t - 1, V, out_probs, out_idx);
        if (t == 0)
            cell_kernel<<<BSZ * HSZ / 256, 256>>>(hbuf[cur ^ 1], pxg0, 0, nullptr);
        else
            cell_kernel<<<BSZ * HSZ / 256, 256>>>(hbuf[cur ^ 1], pxg_dec, XB, psel);
        cur ^= 1;
    }
    gemm_step<<<gg, 256>>>(hbuf[cur], pWdecT, pq, b2, HSZ);
    attn_kernel<<<BSZ, 256>>>(SSZ - 1, V, out_probs, out_idx);
}

// round 11
// speedup vs baseline: 1.1337x; 1.1337x over previous
#include <cuda_runtime.h>
#include <math.h>
#include <stddef.h>

#define BSZ 256
#define SSZ 128
#define ESZ 256
#define HSZ 512
#define GSZ 2048   // 4*H
#define NC  2560   // 2048 gates + 512 (proj or q)
#define NB2 4096   // 2*GSZ combined xg cols

// ---------- device scratch ----------
__device__ float  g_WencT[HSZ * NC];
__device__ float  g_WdecT[HSZ * NC];
__device__ float  g_WihT[ESZ * NB2];
__device__ float  g_emb[(size_t)BSZ * SSZ * ESZ];
__device__ float  g_xg_enc[(size_t)BSZ * SSZ * GSZ];
__device__ float  g_xg_dec[(size_t)BSZ * SSZ * GSZ];
__device__ float  g_proj[(size_t)BSZ * SSZ * HSZ];
__device__ float  g_C[BSZ * GSZ];
__device__ float  g_h[2][BSZ * HSZ];
__device__ float  g_c[BSZ * HSZ];
__device__ float  g_q[BSZ * HSZ];
__device__ float  g_xg0[GSZ];
__device__ float  g_us[BSZ * SSZ];
__device__ int    g_mask[BSZ * SSZ];

// ---------- frozen numerics: libdevice tanh, exp-based logistic ----------
__device__ __forceinline__ float xtanh(float x) { return tanhf(x); }
__device__ __forceinline__ float sigf(float x) {
    return __fdiv_rn(1.0f, __fadd_rn(1.0f, expf(-x)));
}

// ---------- weight transposes ----------
__global__ void transpose_kernel(const float* __restrict__ encWhh, const float* __restrict__ W1,
                                 const float* __restrict__ decWhh, const float* __restrict__ W2) {
    int i = blockIdx.x * blockDim.x + threadIdx.x;
    if (i >= HSZ * NC) return;
    int k = i / NC, n = i % NC;
    g_WencT[i] = (n < GSZ) ? encWhh[n * HSZ + k] : W1[(n - GSZ) * HSZ + k];
    g_WdecT[i] = (n < GSZ) ? decWhh[n * HSZ + k] : W2[(n - GSZ) * HSZ + k];
}
__global__ void wiht_kernel(const float* __restrict__ encWih, const float* __restrict__ decWih) {
    int i = blockIdx.x * blockDim.x + threadIdx.x;
    if (i >= ESZ * NB2) return;
    int k = i / NB2, n = i % NB2;
    g_WihT[i] = (n < GSZ) ? encWih[n * ESZ + k] : decWih[(n - GSZ) * ESZ + k];
}

// ---------- emb: K=2 fma chain + fp32 bias ----------
__global__ void emb_kernel(const float* __restrict__ inputs, const float* __restrict__ embW,
                           const float* __restrict__ embB) {
    int i = blockIdx.x * blockDim.x + threadIdx.x;
    if (i >= BSZ * SSZ * ESZ) return;
    int e = i % ESZ, bs = i / ESZ;
    float in0 = inputs[(size_t)bs * 2], in1 = inputs[(size_t)bs * 2 + 1];
    float mm = fmaf(in1, embW[2 * e + 1], __fmul_rn(in0, embW[2 * e]));
    g_emb[i] = __fadd_rn(mm, embB[e]);
}

// ---------- decoder step-0 input gates ----------
__global__ void xg0_kernel(const float* __restrict__ decWih, const float* __restrict__ dbih,
                           const float* __restrict__ dbhh, const float* __restrict__ dec0) {
    int n = blockIdx.x * blockDim.x + threadIdx.x;
    if (n >= GSZ) return;
    float acc = 0.f;
    for (int e = 0; e < ESZ; e++) acc = fmaf(dec0[e], decWih[n * ESZ + e], acc);
    g_xg0[n] = __fadd_rn(__fadd_rn(acc, dbih[n]), dbhh[n]);
}

// ---------- state init ----------
__global__ void init_kernel(const float* __restrict__ h0, const float* __restrict__ c0,
                            const float* __restrict__ inputs) {
    int i = blockIdx.x * blockDim.x + threadIdx.x;
    if (i < BSZ * HSZ) {
        g_h[0][i] = h0[i & (HSZ - 1)];
        g_c[i]    = c0[i & (HSZ - 1)];
    }
    if (i < BSZ * SSZ) g_mask[i] = (inputs[(size_t)i * 2] > 0.0f) ? 1 : 0;
}

// ---------- xg precompute GEMM: [32768,4096] = emb @ WihT, fp32 ascending ----------
__global__ void __launch_bounds__(256) xg_gemm(const float* __restrict__ ebih, const float* __restrict__ ebhh,
                                               const float* __restrict__ dbih, const float* __restrict__ dbhh) {
    __shared__ __align__(16) float As[16][64 + 4];
    __shared__ __align__(16) float Bs[16][64];
    const int tid = threadIdx.x;
    const int row0 = blockIdx.y * 64;
    const int n0 = blockIdx.x * 64;
    const int lr = tid >> 2, lk = (tid & 3) << 2;
    const int bk = tid >> 4, bn = (tid & 15) << 2;
    const int tm = tid & 15, tn = tid >> 4;

    float acc[4][4];
#pragma unroll
    for (int i = 0; i < 4; i++)
#pragma unroll
        for (int j = 0; j < 4; j++) acc[i][j] = 0.f;

    {
        float4 av = *reinterpret_cast<const float4*>(g_emb + (size_t)(row0 + lr) * ESZ + lk);
        As[lk + 0][lr] = av.x; As[lk + 1][lr] = av.y;
        As[lk + 2][lr] = av.z; As[lk + 3][lr] = av.w;
        *reinterpret_cast<float4*>(&Bs[bk][bn]) =
            *reinterpret_cast<const float4*>(g_WihT + (size_t)bk * NB2 + n0 + bn);
    }
    __syncthreads();

    const int NKC = ESZ / 16;  // 16
    for (int kc = 0; kc < NKC; kc++) {
        float4 av; float4 bv;
        if (kc + 1 < NKC) {
            int k0 = (kc + 1) * 16;
            av = *reinterpret_cast<const float4*>(g_emb + (size_t)(row0 + lr) * ESZ + k0 + lk);
            bv = *reinterpret_cast<const float4*>(g_WihT + (size_t)(k0 + bk) * NB2 + n0 + bn);
        }
#pragma unroll
        for (int k = 0; k < 16; k++) {
            float4 a4 = *reinterpret_cast<const float4*>(&As[k][tm * 4]);
            float4 b4 = *reinterpret_cast<const float4*>(&Bs[k][tn * 4]);
            float ar[4] = {a4.x, a4.y, a4.z, a4.w};
            float br[4] = {b4.x, b4.y, b4.z, b4.w};
#pragma unroll
            for (int i = 0; i < 4; i++)
#pragma unroll
                for (int j = 0; j < 4; j++) acc[i][j] = fmaf(ar[i], br[j], acc[i][j]);
        }
        __syncthreads();
        if (kc + 1 < NKC) {
            As[lk + 0][lr] = av.x; As[lk + 1][lr] = av.y;
            As[lk + 2][lr] = av.z; As[lk + 3][lr] = av.w;
            *reinterpret_cast<float4*>(&Bs[bk][bn]) = bv;
            __syncthreads();
        }
    }

#pragma unroll
    for (int i = 0; i < 4; i++) {
        size_t row = row0 + tm * 4 + i;
#pragma unroll
        for (int j = 0; j < 4; j++) {
            int n = n0 + tn * 4 + j;
            if (n < GSZ)
                g_xg_enc[row * GSZ + n] = __fadd_rn(__fadd_rn(acc[i][j], ebih[n]), ebhh[n]);
            else {
                int nd = n - GSZ;
                g_xg_dec[row * GSZ + nd] = __fadd_rn(__fadd_rn(acc[i][j], dbih[nd]), dbhh[nd]);
            }
        }
    }
}

// ---------- fused step GEMM: [256,2560] = A[256,512] @ WT[512,2560], fp32 ascending ----------
#define BM 64
#define BN 80
#define BK 16
__global__ void __launch_bounds__(256) gemm_step(const float* __restrict__ A,
                                                 const float* __restrict__ WT,
                                                 float* __restrict__ dst2,
                                                 const float* __restrict__ bias2,
                                                 int stride2) {
    __shared__ __align__(16) float As[BK][BM + 4];
    __shared__ __align__(16) float Bs[BK][BN];

    const int tid = threadIdx.x;
    const int tm = tid & 15;
    const int tn = tid >> 4;
    const int row0 = blockIdx.y * BM;
    const int n0 = blockIdx.x * BN;
    const int lr = tid >> 2, lk = (tid & 3) << 2;
    const int bk = tid >> 4, bn = tid & 15;

    float acc[4][5];
#pragma unroll
    for (int i = 0; i < 4; i++)
#pragma unroll
        for (int j = 0; j < 5; j++) acc[i][j] = 0.f;

    {
        float4 av = *reinterpret_cast<const float4*>(A + (size_t)(row0 + lr) * HSZ + lk);
        As[lk + 0][lr] = av.x; As[lk + 1][lr] = av.y;
        As[lk + 2][lr] = av.z; As[lk + 3][lr] = av.w;
#pragma unroll
        for (int j = 0; j < 5; j++)
            Bs[bk][bn + 16 * j] = WT[(size_t)bk * NC + n0 + bn + 16 * j];
    }
    __syncthreads();

    const int NKC = HSZ / BK;  // 32
    for (int kc = 0; kc < NKC; kc++) {
        float4 av;
        float bv[5];
        if (kc + 1 < NKC) {
            int k0 = (kc + 1) * BK;
            av = *reinterpret_cast<const float4*>(A + (size_t)(row0 + lr) * HSZ + k0 + lk);
#pragma unroll
            for (int j = 0; j < 5; j++)
                bv[j] = WT[(size_t)(k0 + bk) * NC + n0 + bn + 16 * j];
        }
#pragma unroll
        for (int k = 0; k < BK; k++) {
            float4 a4 = *reinterpret_cast<const float4*>(&As[k][tm * 4]);
            float ar[4] = {a4.x, a4.y, a4.z, a4.w};
            float br[5];
#pragma unroll
            for (int j = 0; j < 5; j++) br[j] = Bs[k][tn + 16 * j];
#pragma unroll
            for (int i = 0; i < 4; i++)
#pragma unroll
                for (int j = 0; j < 5; j++) acc[i][j] = fmaf(ar[i], br[j], acc[i][j]);
        }
        __syncthreads();
        if (kc + 1 < NKC) {
            As[lk + 0][lr] = av.x; As[lk + 1][lr] = av.y;
            As[lk + 2][lr] = av.z; As[lk + 3][lr] = av.w;
#pragma unroll
            for (int j = 0; j < 5; j++) Bs[bk][bn + 16 * j] = bv[j];
            __syncthreads();
        }
    }

#pragma unroll
    for (int i = 0; i < 4; i++) {
        int b = row0 + tm * 4 + i;
#pragma unroll
        for (int j = 0; j < 5; j++) {
            int n = n0 + tn + 16 * j;
            if (n < GSZ) {
                g_C[(size_t)b * GSZ + n] = acc[i][j];
            } else if (dst2) {
                int n2 = n - GSZ;
                dst2[(size_t)b * stride2 + n2] = __fadd_rn(acc[i][j], bias2[n2]);
            }
        }
    }
}

// ---------- LSTM cell (encoder + decoder step 0) ----------
__global__ void __launch_bounds__(256) cell_kernel(float* __restrict__ h_out,
                                                   const float* __restrict__ xg,
                                                   size_t bstride) {
    int idx = blockIdx.x * blockDim.x + threadIdx.x;
    int b = idx >> 9, hh = idx & (HSZ - 1);
    const float* Cb = g_C + (size_t)b * GSZ;
    const float* xr = xg + (size_t)b * bstride;
    float gi = __fadd_rn(xr[hh],           Cb[hh]);
    float gf = __fadd_rn(xr[HSZ + hh],     Cb[HSZ + hh]);
    float gg = __fadd_rn(xr[2 * HSZ + hh], Cb[2 * HSZ + hh]);
    float go = __fadd_rn(xr[3 * HSZ + hh], Cb[3 * HSZ + hh]);
    float si = sigf(gi), sf = sigf(gf), so = sigf(go);
    float tg = xtanh(gg);
    float cn = __fadd_rn(__fmul_rn(sf, g_c[idx]), __fmul_rn(si, tg));
    g_c[idx] = cn;
    h_out[idx] = __fmul_rn(so, xtanh(cn));
}

// ---------- attention phase 1: u[b,s] dots, full-chip parallel ----------
// grid (BSZ, 8): block q handles s in [q*16, q*16+16); warp w does s = q*16 + w + 8m.
// Per-s arithmetic identical to round-10: lane-strided k ascending + xor tree.
__global__ void __launch_bounds__(256) attn_u_kernel(const float* __restrict__ V) {
    int b = blockIdx.x, qq = blockIdx.y;
    int tid = threadIdx.x, lane = tid & 31, w = tid >> 5;
    __shared__ float qs[HSZ];
    __shared__ float Vs[HSZ];
    for (int i = tid; i < HSZ; i += 256) {
        qs[i] = g_q[(size_t)b * HSZ + i];
        Vs[i] = V[i];
    }
    __syncthreads();
#pragma unroll
    for (int m = 0; m < 2; m++) {
        int s = qq * 16 + w + 8 * m;
        const float* pr = g_proj + ((size_t)b * SSZ + s) * HSZ;
        float acc = 0.f;
        for (int h = lane; h < HSZ; h += 32)
            acc = fmaf(xtanh(__fadd_rn(pr[h], qs[h])), Vs[h], acc);
#pragma unroll
        for (int o = 16; o; o >>= 1)
            acc = __fadd_rn(acc, __shfl_xor_sync(0xffffffffu, acc, o));
        if (lane == 0) g_us[b * SSZ + s] = g_mask[b * SSZ + s] ? acc : -10000.0f;
    }
}

// ---------- attention phase 2: softmax + argmax + mask + fused decoder cell ----------
__global__ void __launch_bounds__(128) attn_fin_kernel(int step,
                                                       float* __restrict__ out_probs,
                                                       float* __restrict__ out_idx,
                                                       float* __restrict__ h_out) {
    int b = blockIdx.x;
    int tid = threadIdx.x, lane = tid & 31, w = tid >> 5;
    __shared__ float us[SSZ];
    __shared__ float es[SSZ];
    __shared__ float ps[SSZ];
    __shared__ float s_mx, s_sum;
    __shared__ int s_idx;

    us[tid] = g_us[b * SSZ + tid];
    __syncthreads();

    if (w == 0) {
        float mv = fmaxf(us[lane], fmaxf(us[lane + 32], fmaxf(us[lane + 64], us[lane + 96])));
#pragma unroll
        for (int o = 16; o; o >>= 1) mv = fmaxf(mv, __shfl_xor_sync(0xffffffffu, mv, o));
        if (lane == 0) s_mx = mv;
    }
    __syncthreads();

    es[tid] = expf(__fadd_rn(us[tid], -s_mx));
    __syncthreads();

    if (w == 0) {
        float sv = __fadd_rn(__fadd_rn(es[lane], es[lane + 32]),
                             __fadd_rn(es[lane + 64], es[lane + 96]));
#pragma unroll
        for (int o = 16; o; o >>= 1)
            sv = __fadd_rn(sv, __shfl_xor_sync(0xffffffffu, sv, o));
        if (lane == 0) s_sum = sv;
    }
    __syncthreads();

    {
        float p = __fdiv_rn(es[tid], s_sum);
        ps[tid] = p;
        out_probs[((size_t)step * BSZ + b) * SSZ + tid] = p;
    }
    __syncthreads();

    if (w == 0) {
        float bv = -1.0f;
        int bi = 0;
#pragma unroll
        for (int k = 0; k < 4; k++) {
            int s = lane + 32 * k;
            float v = ps[s];
            if (v > bv) { bv = v; bi = s; }
        }
#pragma unroll
        for (int o = 16; o; o >>= 1) {
            float ov = __shfl_xor_sync(0xffffffffu, bv, o);
            int oi = __shfl_xor_sync(0xffffffffu, bi, o);
            if (ov > bv || (ov == bv && oi < bi)) { bv = ov; bi = oi; }
        }
        if (lane == 0) s_idx = bi;
    }
    __syncthreads();

    int bi = s_idx;
    if (tid == 0) {
        g_mask[b * SSZ + bi] = 0;
        if (out_idx) out_idx[(size_t)b * SSZ + step] = (float)bi;
    }

    // fused decoder LSTM cell for this iteration (gates already in g_C)
    if (h_out) {
        const float* Cb = g_C + (size_t)b * GSZ;
        const float* xr = g_xg_dec + (size_t)b * ((size_t)SSZ * GSZ) + (size_t)bi * GSZ;
#pragma unroll
        for (int j = 0; j < 4; j++) {
            int hh = tid + 128 * j;
            int idx = b * HSZ + hh;
            float gi = __fadd_rn(xr[hh],           Cb[hh]);
            float gf = __fadd_rn(xr[HSZ + hh],     Cb[HSZ + hh]);
            float gg = __fadd_rn(xr[2 * HSZ + hh], Cb[2 * HSZ + hh]);
            float go = __fadd_rn(xr[3 * HSZ + hh], Cb[3 * HSZ + hh]);
            float si = sigf(gi), sf = sigf(gf), so = sigf(go);
            float tg = xtanh(gg);
            float cn = __fadd_rn(__fmul_rn(sf, g_c[idx]), __fmul_rn(si, tg));
            g_c[idx] = cn;
            h_out[idx] = __fmul_rn(so, xtanh(cn));
        }
    }
}

// ---------- host ----------
extern "C" void kernel_launch(void* const* d_in, const int* in_sizes, int n_in,
                              void* d_out, int out_size) {
    const float* inputs  = (const float*)d_in[0];
    const float* emb_W   = (const float*)d_in[2];
    const float* emb_b   = (const float*)d_in[3];
    const float* enc_Wih = (const float*)d_in[4];
    const float* enc_Whh = (const float*)d_in[5];
    const float* enc_bih = (const float*)d_in[6];
    const float* enc_bhh = (const float*)d_in[7];
    const float* h0      = (const float*)d_in[8];
    const float* c0      = (const float*)d_in[9];
    const float* dec0    = (const float*)d_in[10];
    const float* dec_Wih = (const float*)d_in[11];
    const float* dec_Whh = (const float*)d_in[12];
    const float* dec_bih = (const float*)d_in[13];
    const float* dec_bhh = (const float*)d_in[14];
    const float* W1      = (const float*)d_in[15];
    const float* b1      = (const float*)d_in[16];
    const float* W2      = (const float*)d_in[17];
    const float* b2      = (const float*)d_in[18];
    const float* V       = (const float*)d_in[19];

    float *pWencT, *pWdecT, *pproj, *pq, *ph, *pxg_enc, *pxg_dec, *pxg0;
    cudaGetSymbolAddress((void**)&pWencT,  g_WencT);
    cudaGetSymbolAddress((void**)&pWdecT,  g_WdecT);
    cudaGetSymbolAddress((void**)&pproj,   g_proj);
    cudaGetSymbolAddress((void**)&pq,      g_q);
    cudaGetSymbolAddress((void**)&ph,      g_h);
    cudaGetSymbolAddress((void**)&pxg_enc, g_xg_enc);
    cudaGetSymbolAddress((void**)&pxg_dec, g_xg_dec);
    cudaGetSymbolAddress((void**)&pxg0,    g_xg0);
    float* hbuf[2] = {ph, ph + BSZ * HSZ};

    transpose_kernel<<<(HSZ * NC + 255) / 256, 256>>>(enc_Whh, W1, dec_Whh, W2);
    wiht_kernel<<<(ESZ * NB2 + 255) / 256, 256>>>(enc_Wih, dec_Wih);
    emb_kernel<<<(BSZ * SSZ * ESZ + 255) / 256, 256>>>(inputs, emb_W, emb_b);
    xg0_kernel<<<GSZ / 256, 256>>>(dec_Wih, dec_bih, dec_bhh, dec0);
    init_kernel<<<(BSZ * HSZ + 255) / 256, 256>>>(h0, c0, inputs);
    {
        dim3 gx(NB2 / 64, BSZ * SSZ / 64);  // 64 x 512
        xg_gemm<<<gx, 256>>>(enc_bih, enc_bhh, dec_bih, dec_bhh);
    }

    float* out_probs = (float*)d_out;
    const size_t PROBS_N = (size_t)SSZ * BSZ * SSZ;
    float* out_idx = ((size_t)out_size >= PROBS_N + (size_t)BSZ * SSZ)
                         ? out_probs + PROBS_N : nullptr;

    dim3 gg(NC / BN, BSZ / BM);   // 32 x 4 = 128 blocks
    dim3 ga(BSZ, 8);              // attn_u: 2048 blocks
    const size_t XB = (size_t)SSZ * GSZ;
    int cur = 0;

    // encoder
    for (int t = 0; t < SSZ; t++) {
        gemm_step<<<gg, 256>>>(hbuf[cur], pWencT,
                               (t > 0) ? (pproj + (size_t)(t - 1) * HSZ) : nullptr,
                               b1, SSZ * HSZ);
        cell_kernel<<<BSZ * HSZ / 256, 256>>>(hbuf[cur ^ 1],
                                              pxg_enc + (size_t)t * GSZ, XB);
        cur ^= 1;
    }
    gemm_step<<<gg, 256>>>(hbuf[cur], pWencT, pproj + (size_t)(SSZ - 1) * HSZ, b1, SSZ * HSZ);

    // decoder
    for (int t = 0; t < SSZ; t++) {
        gemm_step<<<gg, 256>>>(hbuf[cur], pWdecT, (t > 0) ? pq : nullptr, b2, HSZ);
        if (t == 0) {
            cell_kernel<<<BSZ * HSZ / 256, 256>>>(hbuf[cur ^ 1], pxg0, 0);
        } else {
            attn_u_kernel<<<ga, 256>>>(V);
            attn_fin_kernel<<<BSZ, 128>>>(t - 1, out_probs, out_idx, hbuf[cur ^ 1]);
        }
        cur ^= 1;
    }
    gemm_step<<<gg, 256>>>(hbuf[cur], pWdecT, pq, b2, HSZ);
    attn_u_kernel<<<ga, 256>>>(V);
    attn_fin_kernel<<<BSZ, 128>>>(SSZ - 1, out_probs, out_idx, nullptr);
}